// round 10
// baseline (speedup 1.0000x reference)
#include <cuda_runtime.h>
#include <cstdint>
#include <math.h>

// SpatialGlimpse fused, one-shot blocks, register-fused separable stencil.
// R10: no hs / no Phase B — each thread accumulates its output(s) in registers
// as 3-row mbarrier groups land (per-lane waits only on groups it reads).
// K=4 outputs split across lane pairs (rows 0-2 / 3-4), combined via shfl.

static constexpr int BATCH  = 64;
static constexpr int H = 512, W = 512, C = 3;
static constexpr int OUTHW  = 64;
static constexpr int NDEPTH = 3;
static constexpr int ROWFL  = W * C;   // 1536 floats per image row
static constexpr int NT     = 256;

static constexpr int RF4 = 780, RF2 = 396, RF1 = 204;   // tile row pitches (floats)
// IR = 9 input rows for every depth; 3 mbarrier groups of 3 rows.

static constexpr int NBLK4 = BATCH * 32;   // TILE_I=2 -> 32 row-tiles/image
static constexpr int NBLK2 = BATCH * 16;   // TILE_I=4
static constexpr int NBLK1 = BATCH * 8;    // TILE_I=8
static constexpr int NBLK  = NBLK4 + NBLK2 + NBLK1;   // 3584

// SMEM floats: [0,8) three mbarriers (8B each at float idx 0,2,4) | tile 9*RF
static constexpr int TILE_OFF   = 8;
static constexpr int SMEM_BYTES = (TILE_OFF + 9 * RF4) * 4;   // 28112

__device__ __forceinline__ uint32_t smem_u32(const void* p) {
    return (uint32_t)__cvta_generic_to_shared(p);
}
__device__ __forceinline__ void mbar_init(uint32_t a, uint32_t cnt) {
    asm volatile("mbarrier.init.shared.b64 [%0], %1;" :: "r"(a), "r"(cnt) : "memory");
}
__device__ __forceinline__ void mbar_expect_tx(uint32_t a, uint32_t bytes) {
    asm volatile("mbarrier.arrive.expect_tx.shared.b64 _, [%0], %1;" :: "r"(a), "r"(bytes) : "memory");
}
__device__ __forceinline__ void mbar_wait(uint32_t a, uint32_t parity) {
    asm volatile(
        "{\n\t"
        ".reg .pred P;\n\t"
        "LAB_WAIT_%=:\n\t"
        "mbarrier.try_wait.parity.acquire.cta.shared::cta.b64 P, [%0], %1, 0x989680;\n\t"
        "@P bra LAB_DONE_%=;\n\t"
        "bra LAB_WAIT_%=;\n\t"
        "LAB_DONE_%=:\n\t"
        "}"
        :: "r"(a), "r"(parity) : "memory");
}
__device__ __forceinline__ void bulk_g2s(uint32_t dst, const void* src, uint32_t bytes, uint32_t mbar) {
    asm volatile(
        "cp.async.bulk.shared::cluster.global.mbarrier::complete_tx::bytes [%0], [%1], %2, [%3];"
        :: "r"(dst), "l"(src), "r"(bytes), "r"(mbar) : "memory");
}

// Horizontal (K+1)-tap weighted sum of one row window, accumulated with
// vertical weight vw. SH = sub-float4 shift (compile-time).
template<int K, int NV, int SH>
__device__ __forceinline__ void hred_acc(const float* __restrict__ rowp, float wx, float vw,
                                         float& a0, float& a1, float& a2)
{
    float v[4 * NV];
    const float4* rp = reinterpret_cast<const float4*>(rowp);
#pragma unroll
    for (int t = 0; t < NV; t++) {
        float4 q = rp[t];
        v[4*t+0]=q.x; v[4*t+1]=q.y; v[4*t+2]=q.z; v[4*t+3]=q.w;
    }
    const float hx0 = 1.0f - wx;
    float r0 = hx0*v[SH+0] + wx*v[SH+3*K+0];
    float r1 = hx0*v[SH+1] + wx*v[SH+3*K+1];
    float r2 = hx0*v[SH+2] + wx*v[SH+3*K+2];
#pragma unroll
    for (int q = 1; q < K; q++) {
        r0 += v[SH+3*q+0]; r1 += v[SH+3*q+1]; r2 += v[SH+3*q+2];
    }
    a0 += vw*r0; a1 += vw*r1; a2 += vw*r2;
}

// ── K=4: lane pairs split one output: s=0 rows 0-2, s=1 rows 3-4 (of the 5). ──
template<int SH>
__device__ __forceinline__ void comp_k4(float* smem, const float* tile, float wx, float wy,
                                        int a0w, float* __restrict__ out, int b, int i0)
{
    const int tid = threadIdx.x;
    const int o = tid >> 1, s = tid & 1;
    const int ti = o >> 6, j = o & 63;
    const int rbase = ti * 4;
    const int rlo = rbase + (s ? 3 : 0);
    const int rhi = rbase + (s ? 4 : 2);
    const float* base = tile + a0w + 12 * j;
    const float wy0 = 1.0f - wy;
    float A0 = 0.f, A1 = 0.f, A2 = 0.f;
#pragma unroll
    for (int g = 0; g < 3; g++) {
        if (rhi >= 3*g && rlo <= 3*g + 2) {
            mbar_wait(smem_u32(smem + 2*g), 0);
#pragma unroll
            for (int r = 3*g; r < 3*g + 3; r++) {
                if (r >= rlo && r <= rhi) {
                    const float vw = (r == rbase) ? wy0 : ((r == rbase + 4) ? wy : 1.0f);
                    hred_acc<4, 5, SH>(base + r * RF4, wx, vw, A0, A1, A2);
                }
            }
        }
    }
    A0 += __shfl_xor_sync(0xffffffffu, A0, 1);
    A1 += __shfl_xor_sync(0xffffffffu, A1, 1);
    A2 += __shfl_xor_sync(0xffffffffu, A2, 1);
    if (s == 0) {
        const size_t ob = (((size_t)b * OUTHW + (i0 + ti)) * OUTHW + j) * (C * NDEPTH);
        out[ob + 2] = A0 * 0.0625f;
        out[ob + 5] = A1 * 0.0625f;
        out[ob + 8] = A2 * 0.0625f;
    }
}

// ── K=2: one thread per output; j = 2*lane + (warp&1) keeps shift warp-uniform. ──
template<int SH>
__device__ __forceinline__ void comp_k2(float* smem, const float* tile, float wx, float wy,
                                        int off0, float* __restrict__ out, int b, int i0)
{
    const int tid = threadIdx.x, w = tid >> 5, l = tid & 31;
    const int ti = w >> 1, j = 2 * l + (w & 1);
    const float* base = tile + ((off0 + 6 * j) & ~3);
    const int rlo = 2 * ti, rhi = 2 * ti + 2;
    const float wy0 = 1.0f - wy;
    float A0 = 0.f, A1 = 0.f, A2 = 0.f;
#pragma unroll
    for (int g = 0; g < 3; g++) {
        if (rhi >= 3*g && rlo <= 3*g + 2) {
            mbar_wait(smem_u32(smem + 2*g), 0);
#pragma unroll
            for (int r = 3*g; r < 3*g + 3; r++) {
                if (r >= rlo && r <= rhi) {
                    const float vw = (r == rlo) ? wy0 : ((r == rhi) ? wy : 1.0f);
                    hred_acc<2, 3, SH>(base + r * RF2, wx, vw, A0, A1, A2);
                }
            }
        }
    }
    const size_t ob = (((size_t)b * OUTHW + (i0 + ti)) * OUTHW + j) * (C * NDEPTH);
    out[ob + 1] = A0 * 0.25f;
    out[ob + 4] = A1 * 0.25f;
    out[ob + 7] = A2 * 0.25f;
}

// ── K=1: two outputs per thread; j = 4*(l&15)+(w&3) keeps shift warp-uniform. ──
template<int SH>
__device__ __forceinline__ void comp_k1(float* smem, const float* tile, float wx, float wy,
                                        int off0, float* __restrict__ out, int b, int i0)
{
    const int tid = threadIdx.x, w = tid >> 5, l = tid & 31;
    const int j  = 4 * (l & 15) + (w & 3);
    const int tb = (l >> 4) + ((w >> 2) << 1);           // 0..3; outputs tb, tb+4
    const float* base = tile + ((off0 + 3 * j) & ~3);
    const float wy0 = 1.0f - wy;
    float A0 = 0.f, A1 = 0.f, A2 = 0.f;   // output tiA = tb   (rows tb, tb+1)
    float B0 = 0.f, B1 = 0.f, B2 = 0.f;   // output tiB = tb+4 (rows tb+4, tb+5)
#pragma unroll
    for (int g = 0; g < 3; g++) {
        const bool needA = (tb + 1 >= 3*g) && (tb <= 3*g + 2);
        const bool needB = (tb + 5 >= 3*g) && (tb + 4 <= 3*g + 2);
        if (needA || needB) {
            mbar_wait(smem_u32(smem + 2*g), 0);
#pragma unroll
            for (int r = 3*g; r < 3*g + 3; r++) {
                if (r == tb)     hred_acc<1, 3, SH>(base + r * RF1, wx, wy0, A0, A1, A2);
                if (r == tb + 1) hred_acc<1, 3, SH>(base + r * RF1, wx, wy,  A0, A1, A2);
                if (r == tb + 4) hred_acc<1, 3, SH>(base + r * RF1, wx, wy0, B0, B1, B2);
                if (r == tb + 5) hred_acc<1, 3, SH>(base + r * RF1, wx, wy,  B0, B1, B2);
            }
        }
    }
    const size_t obA = (((size_t)b * OUTHW + (i0 + tb)) * OUTHW + j) * (C * NDEPTH);
    out[obA + 0] = A0; out[obA + 3] = A1; out[obA + 6] = A2;
    const size_t obB = (((size_t)b * OUTHW + (i0 + tb + 4)) * OUTHW + j) * (C * NDEPTH);
    out[obB + 0] = B0; out[obB + 3] = B1; out[obB + 6] = B2;
}

// Stage: all threads compute geometry; tid0 fires 9 bulk copies into 3 groups;
// everyone zeroes tails/OOB rows; one syncthreads. Returns off0/wx/wy by value.
template<int K, int RF>
__device__ __forceinline__ void stage(
    const float* __restrict__ img, const float* __restrict__ offs,
    float* smem, int b, int i0, float& wy, float& wx, int& off0)
{
    constexpr int IR   = 9;
    constexpr int SPAN = OUTHW * K + 1;
    const int tid = threadIdx.x;
    float* tile = smem + TILE_OFF;

    const float cy = (offs[2*b + 0] + 1.0f) * (H * 0.5f);
    const float cx = (offs[2*b + 1] + 1.0f) * (W * 0.5f);
    const float Ey = cy - (OUTHW * K - 1) * 0.5f;
    const float Ex = cx - (OUTHW * K - 1) * 0.5f;
    const int   y0 = (int)floorf(Ey);
    const int   x0 = (int)floorf(Ex);
    wy = Ey - (float)y0;
    wx = Ex - (float)x0;

    const int x_hi    = min(x0 + SPAN, W);
    const int start_f = (x0 * 3) & ~3;
    const int end_f   = min((x_hi * 3 + 3) & ~3, ROWFL);
    const int validf  = end_f - start_f;
    off0 = x0 * 3 - start_f;                    // 0..3
    const int rowbytes = validf * 4;
    const int ytop    = y0 + i0 * K;

    if (tid == 0) {
#pragma unroll
        for (int g = 0; g < 3; g++) mbar_init(smem_u32(smem + 2*g), 1);
        asm volatile("fence.proxy.async.shared::cta;" ::: "memory");
#pragma unroll
        for (int g = 0; g < 3; g++) {
            int nv = 0;
#pragma unroll
            for (int r = 3*g; r < 3*g + 3; r++)
                if ((unsigned)(ytop + r) < (unsigned)H) nv++;
            mbar_expect_tx(smem_u32(smem + 2*g), (uint32_t)(nv * rowbytes));
        }
#pragma unroll
        for (int r = 0; r < IR; r++) {
            const int gy = ytop + r;
            if ((unsigned)gy < (unsigned)H) {
                const float* src = img + ((size_t)b * H + gy) * ROWFL + start_f;
                bulk_g2s(smem_u32(tile + r * RF), src, (uint32_t)rowbytes, smem_u32(smem + 2*(r/3)));
            }
        }
    }

    // Zero tails (disjoint from bulk-copy dest bytes) and OOB rows.
    {
        const int ntail = RF - validf;          // >= 3 always
        for (int idx = tid; idx < IR * ntail; idx += NT) {
            const int r = idx / ntail;
            tile[r * RF + validf + idx % ntail] = 0.0f;
        }
#pragma unroll
        for (int r = 0; r < IR; r++) {
            if ((unsigned)(ytop + r) >= (unsigned)H) {
                for (int f = tid; f < validf; f += NT) tile[r * RF + f] = 0.0f;
            }
        }
    }
    __syncthreads();   // zeros done + mbar inits visible before any wait
}

__global__ __launch_bounds__(NT, 7)
void glimpse_fused(const float* __restrict__ img, const float* __restrict__ offs,
                   float* __restrict__ out)
{
    extern __shared__ float smem[];
    float* tile = smem + TILE_OFF;
    const int bid = blockIdx.x;
    float wy, wx; int off0;

    if (bid < NBLK4) {                               // K=4: 32 blocks/image
        const int b = bid >> 5, i0 = (bid & 31) * 2;
        stage<4, RF4>(img, offs, smem, b, i0, wy, wx, off0);
        const int a0w = off0 & ~3;                   // 12j keeps mod-4 fixed
        switch (off0 & 3) {
        case 0:  comp_k4<0>(smem, tile, wx, wy, a0w, out, b, i0); break;
        case 1:  comp_k4<1>(smem, tile, wx, wy, a0w, out, b, i0); break;
        case 2:  comp_k4<2>(smem, tile, wx, wy, a0w, out, b, i0); break;
        default: comp_k4<3>(smem, tile, wx, wy, a0w, out, b, i0); break;
        }
    } else if (bid < NBLK4 + NBLK2) {                // K=2: 16 blocks/image
        const int r = bid - NBLK4;
        const int b = r >> 4, i0 = (r & 15) * 4;
        stage<2, RF2>(img, offs, smem, b, i0, wy, wx, off0);
        const int w = threadIdx.x >> 5;
        switch ((off0 + 6 * (w & 1)) & 3) {          // warp-uniform
        case 0:  comp_k2<0>(smem, tile, wx, wy, off0, out, b, i0); break;
        case 1:  comp_k2<1>(smem, tile, wx, wy, off0, out, b, i0); break;
        case 2:  comp_k2<2>(smem, tile, wx, wy, off0, out, b, i0); break;
        default: comp_k2<3>(smem, tile, wx, wy, off0, out, b, i0); break;
        }
    } else {                                         // K=1: 8 blocks/image
        const int r = bid - (NBLK4 + NBLK2);
        const int b = r >> 3, i0 = (r & 7) * 8;
        stage<1, RF1>(img, offs, smem, b, i0, wy, wx, off0);
        const int w = threadIdx.x >> 5;
        switch ((off0 + 3 * (w & 3)) & 3) {          // warp-uniform
        case 0:  comp_k1<0>(smem, tile, wx, wy, off0, out, b, i0); break;
        case 1:  comp_k1<1>(smem, tile, wx, wy, off0, out, b, i0); break;
        case 2:  comp_k1<2>(smem, tile, wx, wy, off0, out, b, i0); break;
        default: comp_k1<3>(smem, tile, wx, wy, off0, out, b, i0); break;
        }
    }
}

extern "C" void kernel_launch(void* const* d_in, const int* in_sizes, int n_in,
                              void* d_out, int out_size)
{
    (void)in_sizes; (void)n_in; (void)out_size;
    const float* img  = (const float*)d_in[0];
    const float* offs = (const float*)d_in[1];
    float* out = (float*)d_out;

    cudaFuncSetAttribute(glimpse_fused, cudaFuncAttributeMaxDynamicSharedMemorySize, SMEM_BYTES);
    glimpse_fused<<<NBLK, NT, SMEM_BYTES>>>(img, offs, out);
}

// round 11
// speedup vs baseline: 1.2827x; 1.2827x over previous
#include <cuda_runtime.h>
#include <cstdint>
#include <math.h>

// SpatialGlimpse fused, one-shot blocks, two-phase separable stencil.
// R11 = R9 pipelining x smaller tiles: IR=5 input rows (TILE_I 1/2/4), two
// mbarrier row-groups (3+2), 7168 blocks, 8 CTAs/SM, parallel copy issue.

static constexpr int BATCH  = 64;
static constexpr int H = 512, W = 512, C = 3;
static constexpr int OUTHW  = 64;
static constexpr int NDEPTH = 3;
static constexpr int ROWFL  = W * C;   // 1536 floats per image row
static constexpr int NT     = 256;

template<int K> struct Cfg;
template<> struct Cfg<1> { static constexpr int TILE_I = 4; static constexpr int ROWF = 204; static constexpr int NV = 3; };
template<> struct Cfg<2> { static constexpr int TILE_I = 2; static constexpr int ROWF = 396; static constexpr int NV = 3; };
template<> struct Cfg<4> { static constexpr int TILE_I = 1; static constexpr int ROWF = 780; static constexpr int NV = 5; };
// IR = TILE_I*K + 1 = 5 input rows for every depth; groups: rows {0,1,2}, {3,4}.

static constexpr int NBLK4 = BATCH * (OUTHW / Cfg<4>::TILE_I);   // 4096
static constexpr int NBLK2 = BATCH * (OUTHW / Cfg<2>::TILE_I);   // 2048
static constexpr int NBLK1 = BATCH * (OUTHW / Cfg<1>::TILE_I);   // 1024
static constexpr int NBLK  = NBLK4 + NBLK2 + NBLK1;              // 7168

// SMEM floats: [0,8) two mbarriers (8B each at float idx 0,2) | tile 5*ROWF | hs 5*64 f4
static constexpr int TILE_OFF   = 8;
static constexpr int SMEM_BYTES = (TILE_OFF + 5 * Cfg<4>::ROWF + 5 * OUTHW * 4) * 4;  // 20752

__device__ __forceinline__ uint32_t smem_u32(const void* p) {
    return (uint32_t)__cvta_generic_to_shared(p);
}
__device__ __forceinline__ void mbar_init(uint32_t a, uint32_t cnt) {
    asm volatile("mbarrier.init.shared.b64 [%0], %1;" :: "r"(a), "r"(cnt) : "memory");
}
__device__ __forceinline__ void mbar_expect_tx(uint32_t a, uint32_t bytes) {
    asm volatile("mbarrier.arrive.expect_tx.shared.b64 _, [%0], %1;" :: "r"(a), "r"(bytes) : "memory");
}
__device__ __forceinline__ void mbar_wait(uint32_t a, uint32_t parity) {
    asm volatile(
        "{\n\t"
        ".reg .pred P;\n\t"
        "LAB_WAIT_%=:\n\t"
        "mbarrier.try_wait.parity.acquire.cta.shared::cta.b64 P, [%0], %1, 0x989680;\n\t"
        "@P bra LAB_DONE_%=;\n\t"
        "bra LAB_WAIT_%=;\n\t"
        "LAB_DONE_%=:\n\t"
        "}"
        :: "r"(a), "r"(parity) : "memory");
}
__device__ __forceinline__ void bulk_g2s(uint32_t dst, const void* src, uint32_t bytes, uint32_t mbar) {
    asm volatile(
        "cp.async.bulk.shared::cluster.global.mbarrier::complete_tx::bytes [%0], [%1], %2, [%3];"
        :: "r"(dst), "l"(src), "r"(bytes), "r"(mbar) : "memory");
}

// Horizontal weighted sum for one (row, j): window of K+1 pixels x 3 channels.
// SH = sub-float4 shift (compile-time so v[] stays in registers).
template<int K, int SH>
__device__ __forceinline__ void hreduce_one(const float* __restrict__ rowp, float wx, float4& h)
{
    constexpr int NV = Cfg<K>::NV;
    const float hx0 = 1.0f - wx;
    float v[4 * NV];
    const float4* rp = reinterpret_cast<const float4*>(rowp);
#pragma unroll
    for (int t = 0; t < NV; t++) {
        float4 q = rp[t];
        v[4*t+0] = q.x; v[4*t+1] = q.y; v[4*t+2] = q.z; v[4*t+3] = q.w;
    }
    float r0 = hx0 * v[SH + 0] + wx * v[SH + 3*K + 0];
    float r1 = hx0 * v[SH + 1] + wx * v[SH + 3*K + 1];
    float r2 = hx0 * v[SH + 2] + wx * v[SH + 3*K + 2];
#pragma unroll
    for (int q = 1; q < K; q++) {
        r0 += v[SH + 3*q + 0];
        r1 += v[SH + 3*q + 1];
        r2 += v[SH + 3*q + 2];
    }
    h.x = r0; h.y = r1; h.z = r2; h.w = 0.0f;
}

// Phase A for one row r (all j): writes hs[r*64 + j]. Called with tid-derived (r,j).
template<int K>
__device__ __forceinline__ void phaseA_row(
    const float* __restrict__ tile, float4* __restrict__ hs,
    int r, int j, int off0, float wx)
{
    constexpr int RF = Cfg<K>::ROWF;
    const int sidx = off0 + 3 * K * j;
    const int a0   = sidx & ~3;
    const float* rowp = tile + r * RF + a0;
    float4 h;
    switch (sidx & 3) {
    case 0:  hreduce_one<K,0>(rowp, wx, h); break;
    case 1:  hreduce_one<K,1>(rowp, wx, h); break;
    case 2:  hreduce_one<K,2>(rowp, wx, h); break;
    default: hreduce_one<K,3>(rowp, wx, h); break;
    }
    hs[r * OUTHW + j] = h;
}

template<int K, int D>
__device__ __forceinline__ void glimpse_body(
    const float* __restrict__ img, const float* __restrict__ offs,
    float* __restrict__ out, float* smem, int b, int i0)
{
    constexpr int TILE_I = Cfg<K>::TILE_I;
    constexpr int RF     = Cfg<K>::ROWF;
    constexpr int IR     = 5;
    constexpr int SPAN   = OUTHW * K + 1;

    float* tile = smem + TILE_OFF;
    float4* hs  = reinterpret_cast<float4*>(smem + TILE_OFF + IR * RF);
    const int tid = threadIdx.x;
    const uint32_t mb0 = smem_u32(smem);
    const uint32_t mb1 = smem_u32(smem + 2);

    // All threads compute geometry in parallel.
    const float cy = (offs[2*b + 0] + 1.0f) * (H * 0.5f);
    const float cx = (offs[2*b + 1] + 1.0f) * (W * 0.5f);
    const float Ey = cy - (OUTHW * K - 1) * 0.5f;
    const float Ex = cx - (OUTHW * K - 1) * 0.5f;
    const int   y0 = (int)floorf(Ey);
    const int   x0 = (int)floorf(Ex);
    const float wy = Ey - (float)y0;
    const float wx = Ex - (float)x0;

    const int x_hi    = min(x0 + SPAN, W);
    const int start_f = (x0 * 3) & ~3;
    const int end_f   = min((x_hi * 3 + 3) & ~3, ROWFL);
    const int validf  = end_f - start_f;
    const int off0    = x0 * 3 - start_f;       // 0..3
    const int rowbytes = validf * 4;            // multiple of 16
    const int ytop    = y0 + i0 * K;

    // Warp 0: lane 0 inits mbars + fence + expectations; lanes 0-4 issue one
    // row copy each in parallel.
    if (tid < 32) {
        if (tid == 0) {
            mbar_init(mb0, 1);
            mbar_init(mb1, 1);
            asm volatile("fence.proxy.async.shared::cta;" ::: "memory");
            int nv0 = 0, nv1 = 0;
#pragma unroll
            for (int r = 0; r < 3; r++) if ((unsigned)(ytop + r) < (unsigned)H) nv0++;
#pragma unroll
            for (int r = 3; r < 5; r++) if ((unsigned)(ytop + r) < (unsigned)H) nv1++;
            mbar_expect_tx(mb0, (uint32_t)(nv0 * rowbytes));
            mbar_expect_tx(mb1, (uint32_t)(nv1 * rowbytes));
        }
        __syncwarp();
        if (tid < IR) {
            const int gy = ytop + tid;
            if ((unsigned)gy < (unsigned)H) {
                const float* src = img + ((size_t)b * H + gy) * ROWFL + start_f;
                bulk_g2s(smem_u32(tile + tid * RF), src, (uint32_t)rowbytes,
                         tid < 3 ? mb0 : mb1);
            }
        }
    }

    // Meanwhile: zero tails (disjoint from bulk-copy dest bytes) and OOB rows.
    {
        const int ntail = RF - validf;          // >= 3 always
        for (int idx = tid; idx < IR * ntail; idx += NT) {
            const int r = idx / ntail;
            tile[r * RF + validf + idx % ntail] = 0.0f;
        }
#pragma unroll
        for (int r = 0; r < IR; r++) {
            if ((unsigned)(ytop + r) >= (unsigned)H) {
                for (int f = tid; f < validf; f += NT) tile[r * RF + f] = 0.0f;
            }
        }
    }
    __syncthreads();   // zeros done + mbar inits visible to all warps

    // ── Phase A, pipelined: group 0 = rows 0-2 (192 threads), group 1 = rows 3-4. ──
    mbar_wait(mb0, 0);
    if (tid < 3 * OUTHW) {
        phaseA_row<K>(tile, hs, tid >> 6, tid & 63, off0, wx);
    }
    mbar_wait(mb1, 0);
    if (tid < 2 * OUTHW) {
        phaseA_row<K>(tile, hs, 3 + (tid >> 6), tid & 63, off0, wx);
    }
    __syncthreads();

    // ── Phase B: vertical (K+1)-tap over hs. TILE_I*64 outputs (<=256). ──
    constexpr float inv = 1.0f / (K * K);
    const float wy0 = 1.0f - wy;
    if (tid < TILE_I * OUTHW) {
        const int ti = tid >> 6;
        const int jj = tid & 63;
        float4 a = hs[(ti * K) * OUTHW + jj];
        float o0 = wy0 * a.x, o1 = wy0 * a.y, o2 = wy0 * a.z;
#pragma unroll
        for (int p = 1; p < K; p++) {
            float4 m = hs[(ti * K + p) * OUTHW + jj];
            o0 += m.x; o1 += m.y; o2 += m.z;
        }
        float4 e = hs[(ti * K + K) * OUTHW + jj];
        o0 += wy * e.x; o1 += wy * e.y; o2 += wy * e.z;

        const size_t ob = (((size_t)b * OUTHW + (i0 + ti)) * OUTHW + jj) * (C * NDEPTH);
        out[ob + 0 * NDEPTH + D] = o0 * inv;
        out[ob + 1 * NDEPTH + D] = o1 * inv;
        out[ob + 2 * NDEPTH + D] = o2 * inv;
    }
}

__global__ __launch_bounds__(NT, 8)
void glimpse_fused(const float* __restrict__ img, const float* __restrict__ offs,
                   float* __restrict__ out)
{
    extern __shared__ float smem[];
    const int bid = blockIdx.x;
    if (bid < NBLK4) {                                   // K=4: 64 blocks/image
        glimpse_body<4, 2>(img, offs, out, smem, bid >> 6, bid & 63);
    } else if (bid < NBLK4 + NBLK2) {                    // K=2: 32 blocks/image
        const int r = bid - NBLK4;
        glimpse_body<2, 1>(img, offs, out, smem, r >> 5, (r & 31) * 2);
    } else {                                             // K=1: 16 blocks/image
        const int r = bid - (NBLK4 + NBLK2);
        glimpse_body<1, 0>(img, offs, out, smem, r >> 4, (r & 15) * 4);
    }
}

extern "C" void kernel_launch(void* const* d_in, const int* in_sizes, int n_in,
                              void* d_out, int out_size)
{
    (void)in_sizes; (void)n_in; (void)out_size;
    const float* img  = (const float*)d_in[0];
    const float* offs = (const float*)d_in[1];
    float* out = (float*)d_out;

    cudaFuncSetAttribute(glimpse_fused, cudaFuncAttributeMaxDynamicSharedMemorySize, SMEM_BYTES);
    glimpse_fused<<<NBLK, NT, SMEM_BYTES>>>(img, offs, out);
}